// round 3
// baseline (speedup 1.0000x reference)
#include <cuda_runtime.h>
#include <cstdint>

#define N_NODES 50000
#define D 128

// Scratch (alloc-free rule: __device__ globals). float4 => 16B alignment for red.v4.
__device__ float4 g_agg4[(size_t)N_NODES * (D / 4)];
__device__ int    g_cnt[N_NODES];
__device__ float  g_rinv[N_NODES];

// ---------------------------------------------------------------------------
// Kernel 1: zero aggregation buffer + counts
// ---------------------------------------------------------------------------
__global__ void k_zero() {
    size_t i = (size_t)blockIdx.x * blockDim.x + threadIdx.x;
    size_t stride = (size_t)gridDim.x * blockDim.x;
    size_t n4 = (size_t)N_NODES * (D / 4);
    float4 z = make_float4(0.f, 0.f, 0.f, 0.f);
    for (size_t j = i; j < n4; j += stride) g_agg4[j] = z;
    for (size_t j = i; j < (size_t)N_NODES; j += stride) g_cnt[j] = 0;
}

// ---------------------------------------------------------------------------
// Kernel 2: scatter-add. One warp per edge; lane l handles floats [4l,4l+4).
// Templated on index type (int32 vs int64 resolved host-side via in_sizes).
// x-row gather = coalesced 512B read (x fits in L2). v4 RED quarters the
// L2 atomic-op count vs scalar atomicAdd.
// ---------------------------------------------------------------------------
template <typename IdxT>
__global__ void k_scatter(const float* __restrict__ x,
                          const IdxT* __restrict__ ei, int E) {
    int gw   = (int)((blockIdx.x * (size_t)blockDim.x + threadIdx.x) >> 5);
    int lane = threadIdx.x & 31;
    if (gw >= E) return;

    int s = (int)ei[gw];                  // source (message)
    int t = (int)ei[(size_t)E + gw];      // target (aggregate)

    float4 m = reinterpret_cast<const float4*>(x + (size_t)s * D)[lane];
    float4* a = g_agg4 + (size_t)t * (D / 4) + lane;
    asm volatile("red.global.add.v4.f32 [%0], {%1, %2, %3, %4};"
                 :: "l"(a), "f"(m.x), "f"(m.y), "f"(m.z), "f"(m.w)
                 : "memory");
    if (lane == 0) atomicAdd(&g_cnt[t], 1);
}

// ---------------------------------------------------------------------------
// Kernel 3: reciprocal counts (mean folded into GEMM A-load)
// ---------------------------------------------------------------------------
__global__ void k_rinv() {
    int i = blockIdx.x * blockDim.x + threadIdx.x;
    if (i < N_NODES) {
        int c = g_cnt[i];
        g_rinv[i] = 1.0f / (float)(c > 0 ? c : 1);
    }
}

// ---------------------------------------------------------------------------
// Kernel 4: out = [x | agg*rinv] @ W.  Virtual A [N,256]; each K-chunk of 8
// lies wholly in one half -> pick base + scale per chunk. 128x128 tile,
// 256 threads, 8x8 microtile.
// ---------------------------------------------------------------------------
__global__ void __launch_bounds__(256)
k_gemm(const float* __restrict__ x, const float* __restrict__ W,
       float* __restrict__ out) {
    __shared__ float As[8][128];
    __shared__ float Bs[8][128];

    int tid = threadIdx.x;
    int tx = tid & 15;
    int ty = tid >> 4;
    int row0 = blockIdx.x * 128;

    int lm = tid >> 1;          // A loader row within tile
    int lk = (tid & 1) * 4;     // A loader k-offset
    int bk = tid >> 5;          // B loader k
    int bn = (tid & 31) * 4;    // B loader n

    int arow = row0 + lm;
    if (arow >= N_NODES) arow = N_NODES - 1;   // clamp; stores guarded
    float rs = g_rinv[arow];
    const float* aggrow = reinterpret_cast<const float*>(g_agg4) + (size_t)arow * D;

    float acc[8][8];
#pragma unroll
    for (int i = 0; i < 8; i++)
#pragma unroll
        for (int j = 0; j < 8; j++) acc[i][j] = 0.f;

    for (int k0 = 0; k0 < 256; k0 += 8) {
        const float* abase;
        float scale;
        if (k0 < 128) { abase = x + (size_t)arow * D + k0; scale = 1.f; }
        else          { abase = aggrow + (k0 - 128);       scale = rs;  }
        float4 av = *reinterpret_cast<const float4*>(abase + lk);
        As[lk + 0][lm] = av.x * scale;
        As[lk + 1][lm] = av.y * scale;
        As[lk + 2][lm] = av.z * scale;
        As[lk + 3][lm] = av.w * scale;

        float4 bv = *reinterpret_cast<const float4*>(W + (size_t)(k0 + bk) * 128 + bn);
        *reinterpret_cast<float4*>(&Bs[bk][bn]) = bv;

        __syncthreads();

#pragma unroll
        for (int kk = 0; kk < 8; kk++) {
            float a[8], b[8];
            *reinterpret_cast<float4*>(a)     = *reinterpret_cast<const float4*>(&As[kk][ty * 8]);
            *reinterpret_cast<float4*>(a + 4) = *reinterpret_cast<const float4*>(&As[kk][ty * 8 + 4]);
            *reinterpret_cast<float4*>(b)     = *reinterpret_cast<const float4*>(&Bs[kk][tx * 8]);
            *reinterpret_cast<float4*>(b + 4) = *reinterpret_cast<const float4*>(&Bs[kk][tx * 8 + 4]);
#pragma unroll
            for (int i = 0; i < 8; i++)
#pragma unroll
                for (int j = 0; j < 8; j++)
                    acc[i][j] += a[i] * b[j];
        }
        __syncthreads();
    }

#pragma unroll
    for (int i = 0; i < 8; i++) {
        int row = row0 + ty * 8 + i;
        if (row < N_NODES) {
            float4 o0 = make_float4(acc[i][0], acc[i][1], acc[i][2], acc[i][3]);
            float4 o1 = make_float4(acc[i][4], acc[i][5], acc[i][6], acc[i][7]);
            *reinterpret_cast<float4*>(out + (size_t)row * 128 + tx * 8)     = o0;
            *reinterpret_cast<float4*>(out + (size_t)row * 128 + tx * 8 + 4) = o1;
        }
    }
}

// ---------------------------------------------------------------------------
extern "C" void kernel_launch(void* const* d_in, const int* in_sizes, int n_in,
                              void* d_out, int out_size) {
    const float* x  = (const float*)d_in[0];
    const float* W  = (const float*)d_in[2];    // [256, 128]
    float* out = (float*)d_out;

    // edge_index nominally int64 [2, E=800000]. JAX-x64-off usually downcasts
    // to int32. Disambiguate via the reported element count:
    //   2*E elements  -> genuinely int32
    //   4*E elements  -> int64 payload surfaced as 4-byte elements
    int nelem = in_sizes[1];
    int E;
    bool is64;
    if (nelem == 2 * 800000)      { E = 800000;   is64 = false; }
    else if (nelem == 4 * 800000) { E = 800000;   is64 = true;  }
    else                          { E = nelem / 2; is64 = false; }

    k_zero<<<592, 256>>>();
    size_t threads_total = (size_t)E * 32;      // one warp per edge
    unsigned blocks = (unsigned)((threads_total + 255) / 256);
    if (is64)
        k_scatter<long long><<<blocks, 256>>>(x, (const long long*)d_in[1], E);
    else
        k_scatter<int><<<blocks, 256>>>(x, (const int*)d_in[1], E);
    k_rinv<<<(N_NODES + 255) / 256, 256>>>();
    k_gemm<<<(N_NODES + 127) / 128, 256>>>(x, W, out);
}

// round 8
// speedup vs baseline: 1.2081x; 1.2081x over previous
#include <cuda_runtime.h>
#include <cuda_bf16.h>
#include <cstdint>

#define N_NODES 50000
#define D 128
#define TILES 391            // ceil(50000/128)

// ---------------- scratch (__device__ globals; alloc-free rule) ------------
__device__ float4 g_agg4[(size_t)N_NODES * (D / 4)];
__device__ int    g_cnt[N_NODES];
__device__ float  g_rinv[N_NODES];
// W^T split: [128 n][256 k] bf16 hi/lo, row-major. 128*32 = 4096 uint4 each.
__device__ uint4  g_bhi16[4096];
__device__ uint4  g_blo16[4096];

// ---------------- GEMM geometry --------------------------------------------
#define SA 72                 // A smem row stride (bf16 elems): 64 + 8 pad
#define SB 264                // B smem row stride: 256 + 8 pad
#define A_MAT_BYTES (128 * SA * 2)        // 18432
#define B_MAT_BYTES (128 * SB * 2)        // 67584
#define OFF_A(buf)  ((buf) * 2 * A_MAT_BYTES)             // hi at +0, lo at +A_MAT_BYTES
#define OFF_BHI     (2 * 2 * A_MAT_BYTES)                 // 73728
#define OFF_BLO     (OFF_BHI + B_MAT_BYTES)               // 141312
#define SMEM_TOT    (OFF_BLO + B_MAT_BYTES)               // 208896

__device__ __forceinline__ uint32_t smem_u32(const void* p) {
    uint32_t a;
    asm("{ .reg .u64 t; cvta.to.shared.u64 t, %1; cvt.u32.u64 %0, t; }"
        : "=r"(a) : "l"(p));
    return a;
}

#define LDSM4(r0, r1, r2, r3, addr)                                          \
    asm volatile("ldmatrix.sync.aligned.m8n8.x4.shared.b16 {%0,%1,%2,%3}, [%4];" \
                 : "=r"(r0), "=r"(r1), "=r"(r2), "=r"(r3) : "r"(addr))

#define MMA(d, a, b)                                                          \
    asm volatile("mma.sync.aligned.m16n8k16.row.col.f32.bf16.bf16.f32 "       \
                 "{%0,%1,%2,%3}, {%4,%5,%6,%7}, {%8,%9}, {%0,%1,%2,%3};"      \
                 : "+f"((d)[0]), "+f"((d)[1]), "+f"((d)[2]), "+f"((d)[3])     \
                 : "r"((a)[0]), "r"((a)[1]), "r"((a)[2]), "r"((a)[3]),        \
                   "r"((b)[0]), "r"((b)[1]))

// ---------------------------------------------------------------------------
// Kernel 1: zero agg + counts
// ---------------------------------------------------------------------------
__global__ void k_zero() {
    size_t i = (size_t)blockIdx.x * blockDim.x + threadIdx.x;
    size_t stride = (size_t)gridDim.x * blockDim.x;
    size_t n4 = (size_t)N_NODES * (D / 4);
    float4 z = make_float4(0.f, 0.f, 0.f, 0.f);
    for (size_t j = i; j < n4; j += stride) g_agg4[j] = z;
    for (size_t j = i; j < (size_t)N_NODES; j += stride) g_cnt[j] = 0;
}

// ---------------------------------------------------------------------------
// Kernel 2: scatter-add (warp per edge, v4 RED). Index type templated.
// ---------------------------------------------------------------------------
template <typename IdxT>
__global__ void k_scatter(const float* __restrict__ x,
                          const IdxT* __restrict__ ei, int E) {
    int gw   = (int)((blockIdx.x * (size_t)blockDim.x + threadIdx.x) >> 5);
    int lane = threadIdx.x & 31;
    if (gw >= E) return;
    int s = (int)ei[gw];
    int t = (int)ei[(size_t)E + gw];
    float4 m = reinterpret_cast<const float4*>(x + (size_t)s * D)[lane];
    float4* a = g_agg4 + (size_t)t * (D / 4) + lane;
    asm volatile("red.global.add.v4.f32 [%0], {%1, %2, %3, %4};"
                 :: "l"(a), "f"(m.x), "f"(m.y), "f"(m.z), "f"(m.w) : "memory");
    if (lane == 0) atomicAdd(&g_cnt[t], 1);
}

// ---------------------------------------------------------------------------
// Kernel 3: reciprocal counts
// ---------------------------------------------------------------------------
__global__ void k_rinv() {
    int i = blockIdx.x * blockDim.x + threadIdx.x;
    if (i < N_NODES) {
        int c = g_cnt[i];
        g_rinv[i] = 1.0f / (float)(c > 0 ? c : 1);
    }
}

// ---------------------------------------------------------------------------
// Kernel 3b: W -> W^T bf16 hi/lo split, row-major [n][256]
// ---------------------------------------------------------------------------
__global__ void k_prep_w(const float* __restrict__ W) {
    int id = blockIdx.x * blockDim.x + threadIdx.x;   // 4096 threads
    if (id >= 128 * 32) return;
    int n  = id >> 5;
    int k0 = (id & 31) * 8;
    unsigned short hi[8], lo[8];
#pragma unroll
    for (int j = 0; j < 8; j++) {
        float v = W[(size_t)(k0 + j) * 128 + n];      // W[k][n]
        __nv_bfloat16 h = __float2bfloat16(v);
        __nv_bfloat16 l = __float2bfloat16(v - __bfloat162float(h));
        hi[j] = __bfloat16_as_ushort(h);
        lo[j] = __bfloat16_as_ushort(l);
    }
    g_bhi16[n * 32 + (k0 >> 3)] = *reinterpret_cast<uint4*>(hi);
    g_blo16[n * 32 + (k0 >> 3)] = *reinterpret_cast<uint4*>(lo);
}

// ---------------------------------------------------------------------------
// Kernel 4: bf16 mma.sync GEMM with fused fp32->hi/lo split + mean scaling.
// out = [x | agg*rinv] @ W via D = Ahi Bhi + Ahi Blo + Alo Bhi.
// CTA: 128x128 tile. B fully smem-resident; A in K-chunks of 64,
// next chunk preloaded to regs during compute.
// ---------------------------------------------------------------------------
__global__ void __launch_bounds__(256)
k_gemm_mma(const float* __restrict__ x, float* __restrict__ out) {
    extern __shared__ char smem[];
    const uint32_t sbase = smem_u32(smem);
    const int tid  = threadIdx.x;
    const int wid  = tid >> 5;
    const int lane = tid & 31;
    const int wm   = wid >> 1;          // 0..3 -> m offset 32*wm
    const int wn   = wid & 1;           // 0..1 -> n offset 64*wn
    const int tile = blockIdx.x;

    // ---- load all of B (hi+lo) into smem with padding ----
    {
        uint4* bh = reinterpret_cast<uint4*>(smem + OFF_BHI);
        uint4* bl = reinterpret_cast<uint4*>(smem + OFF_BLO);
        for (int i = tid; i < 4096; i += 256) {
            int row = i >> 5, c16 = i & 31;
            bh[row * 33 + c16] = g_bhi16[i];
            bl[row * 33 + c16] = g_blo16[i];
        }
    }

    // ---- A loader mapping: thread -> row tid/2, 32 cols at (tid&1)*32 ----
    const int ar  = tid >> 1;
    const int acb = (tid & 1) * 32;
    const int gr  = tile * 128 + ar;
    const bool valid = gr < N_NODES;
    const float myrinv = valid ? g_rinv[gr] : 0.f;

    float4 pre[8];
    float  prescale;

    auto preload = [&](int c) {
        const float* src;
        if (c < 2) { src = x + (size_t)gr * D + c * 64 + acb; prescale = 1.f; }
        else { src = reinterpret_cast<const float*>(g_agg4) + (size_t)gr * D + (c - 2) * 64 + acb;
               prescale = myrinv; }
        if (valid) {
#pragma unroll
            for (int j = 0; j < 8; j++) pre[j] = reinterpret_cast<const float4*>(src)[j];
        } else {
#pragma unroll
            for (int j = 0; j < 8; j++) pre[j] = make_float4(0.f, 0.f, 0.f, 0.f);
        }
    };
    auto store_chunk = [&](int buf) {
        uint4* dh = reinterpret_cast<uint4*>(smem + OFF_A(buf));
        uint4* dl = reinterpret_cast<uint4*>(smem + OFF_A(buf) + A_MAT_BYTES);
#pragma unroll
        for (int g = 0; g < 4; g++) {
            float f[8];
            *reinterpret_cast<float4*>(f)     = pre[2 * g];
            *reinterpret_cast<float4*>(f + 4) = pre[2 * g + 1];
            unsigned short hi[8], lo[8];
#pragma unroll
            for (int j = 0; j < 8; j++) {
                float v = f[j] * prescale;
                __nv_bfloat16 h = __float2bfloat16(v);
                __nv_bfloat16 l = __float2bfloat16(v - __bfloat162float(h));
                hi[j] = __bfloat16_as_ushort(h);
                lo[j] = __bfloat16_as_ushort(l);
            }
            int idx = ar * 9 + (acb >> 3) + g;   // SA*2/16 = 9 uint4 per row
            dh[idx] = *reinterpret_cast<uint4*>(hi);
            dl[idx] = *reinterpret_cast<uint4*>(lo);
        }
    };

    preload(0);
    store_chunk(0);
    __syncthreads();

    // ---- ldmatrix lane addressing ----
    const int rL   = (lane & 7) + ((lane >> 3) & 1) * 8;  // row within 16
    const int col8 = (lane >> 4) * 8;                     // k half
    const uint32_t aBaseRow = (uint32_t)((32 * wm + rL) * SA + col8) * 2;
    const uint32_t bHiBase  = sbase + OFF_BHI + (uint32_t)((64 * wn + rL) * SB + col8) * 2;

    float acc[2][8][4];
#pragma unroll
    for (int mi = 0; mi < 2; mi++)
#pragma unroll
        for (int ni = 0; ni < 8; ni++)
#pragma unroll
            for (int q = 0; q < 4; q++) acc[mi][ni][q] = 0.f;

    for (int c = 0; c < 4; c++) {
        if (c < 3) preload(c + 1);

        const uint32_t aHi = sbase + OFF_A(c & 1) + aBaseRow;
        const uint32_t aLo = aHi + A_MAT_BYTES;
        const uint32_t bC  = (uint32_t)c * 128;    // chunk k-offset: 64 bf16 = 128 B
#pragma unroll
        for (int ks = 0; ks < 4; ks++) {
            const uint32_t ko = ks * 32;               // 16 bf16 = 32 bytes
            uint32_t ahi[2][4], alo[2][4], bhi[8][2], blo[8][2];
            LDSM4(ahi[0][0], ahi[0][1], ahi[0][2], ahi[0][3], aHi + ko);
            LDSM4(ahi[1][0], ahi[1][1], ahi[1][2], ahi[1][3], aHi + ko + 16 * SA * 2);
            LDSM4(alo[0][0], alo[0][1], alo[0][2], alo[0][3], aLo + ko);
            LDSM4(alo[1][0], alo[1][1], alo[1][2], alo[1][3], aLo + ko + 16 * SA * 2);
#pragma unroll
            for (int nb = 0; nb < 4; nb++) {
                uint32_t t0, t1, t2, t3;
                LDSM4(t0, t1, t2, t3, bHiBase + bC + ko + nb * 16 * SB * 2);
                bhi[2 * nb][0] = t0; bhi[2 * nb][1] = t2;
                bhi[2 * nb + 1][0] = t1; bhi[2 * nb + 1][1] = t3;
                LDSM4(t0, t1, t2, t3, bHiBase + B_MAT_BYTES + bC + ko + nb * 16 * SB * 2);
                blo[2 * nb][0] = t0; blo[2 * nb][1] = t2;
                blo[2 * nb + 1][0] = t1; blo[2 * nb + 1][1] = t3;
            }
#pragma unroll
            for (int mi = 0; mi < 2; mi++)
#pragma unroll
                for (int ni = 0; ni < 8; ni++) {
                    MMA(acc[mi][ni], ahi[mi], bhi[ni]);
                    MMA(acc[mi][ni], ahi[mi], blo[ni]);
                    MMA(acc[mi][ni], alo[mi], bhi[ni]);
                }
        }

        if (c < 3) store_chunk((c + 1) & 1);
        __syncthreads();
    }

    // ---- epilogue: fp32 stores ----
#pragma unroll
    for (int mi = 0; mi < 2; mi++) {
        int r0 = tile * 128 + 32 * wm + 16 * mi + (lane >> 2);
        int r1 = r0 + 8;
#pragma unroll
        for (int ni = 0; ni < 8; ni++) {
            int colo = 64 * wn + 8 * ni + 2 * (lane & 3);
            if (r0 < N_NODES)
                *reinterpret_cast<float2*>(out + (size_t)r0 * 128 + colo) =
                    make_float2(acc[mi][ni][0], acc[mi][ni][1]);
            if (r1 < N_NODES)
                *reinterpret_cast<float2*>(out + (size_t)r1 * 128 + colo) =
                    make_float2(acc[mi][ni][2], acc[mi][ni][3]);
        }
    }
}

// ---------------------------------------------------------------------------
extern "C" void kernel_launch(void* const* d_in, const int* in_sizes, int n_in,
                              void* d_out, int out_size) {
    const float* x = (const float*)d_in[0];
    const float* W = (const float*)d_in[2];
    float* out = (float*)d_out;

    int nelem = in_sizes[1];
    int E; bool is64;
    if (nelem == 2 * 800000)      { E = 800000;    is64 = false; }
    else if (nelem == 4 * 800000) { E = 800000;    is64 = true;  }
    else                          { E = nelem / 2; is64 = false; }

    cudaFuncSetAttribute(k_gemm_mma, cudaFuncAttributeMaxDynamicSharedMemorySize, SMEM_TOT);

    k_zero<<<592, 256>>>();
    k_prep_w<<<16, 256>>>(W);
    size_t threads_total = (size_t)E * 32;
    unsigned blocks = (unsigned)((threads_total + 255) / 256);
    if (is64)
        k_scatter<long long><<<blocks, 256>>>(x, (const long long*)d_in[1], E);
    else
        k_scatter<int><<<blocks, 256>>>(x, (const int*)d_in[1], E);
    k_rinv<<<(N_NODES + 255) / 256, 256>>>();
    k_gemm_mma<<<TILES, 256, SMEM_TOT>>>(x, out);
}

// round 9
// speedup vs baseline: 1.2230x; 1.0123x over previous
#include <cuda_runtime.h>
#include <cuda_bf16.h>
#include <cstdint>

#define N_NODES 50000
#define D 128
#define TILES 391            // ceil(50000/128)

// ---------------- scratch (__device__ globals; alloc-free rule) ------------
__device__ float4 g_agg4[(size_t)N_NODES * (D / 4)];
__device__ int    g_cnt[N_NODES];
// W^T split: [128 n][256 k] bf16 hi/lo, row-major. 128*32 = 4096 uint4 each.
__device__ uint4  g_bhi16[4096];
__device__ uint4  g_blo16[4096];

// ---------------- GEMM geometry --------------------------------------------
#define SA 72                 // A smem row stride (bf16 elems): 64 + 8 pad
#define SB 264                // B smem row stride: 256 + 8 pad
#define A_MAT_BYTES (128 * SA * 2)        // 18432
#define B_MAT_BYTES (128 * SB * 2)        // 67584
#define OFF_A(buf)  ((buf) * 2 * A_MAT_BYTES)             // hi at +0, lo at +A_MAT_BYTES
#define OFF_BHI     (2 * 2 * A_MAT_BYTES)                 // 73728
#define OFF_BLO     (OFF_BHI + B_MAT_BYTES)               // 141312
#define SMEM_TOT    (OFF_BLO + B_MAT_BYTES)               // 208896

__device__ __forceinline__ uint32_t smem_u32(const void* p) {
    uint32_t a;
    asm("{ .reg .u64 t; cvta.to.shared.u64 t, %1; cvt.u32.u64 %0, t; }"
        : "=r"(a) : "l"(p));
    return a;
}

#define LDSM4(r0, r1, r2, r3, addr)                                          \
    asm volatile("ldmatrix.sync.aligned.m8n8.x4.shared.b16 {%0,%1,%2,%3}, [%4];" \
                 : "=r"(r0), "=r"(r1), "=r"(r2), "=r"(r3) : "r"(addr))

#define MMA(d, a, b)                                                          \
    asm volatile("mma.sync.aligned.m16n8k16.row.col.f32.bf16.bf16.f32 "       \
                 "{%0,%1,%2,%3}, {%4,%5,%6,%7}, {%8,%9}, {%0,%1,%2,%3};"      \
                 : "+f"((d)[0]), "+f"((d)[1]), "+f"((d)[2]), "+f"((d)[3])     \
                 : "r"((a)[0]), "r"((a)[1]), "r"((a)[2]), "r"((a)[3]),        \
                   "r"((b)[0]), "r"((b)[1]))

// ---------------------------------------------------------------------------
// Kernel 1: init — zero agg + counts AND build W^T bf16 hi/lo blobs
// ---------------------------------------------------------------------------
__global__ void k_init(const float* __restrict__ W) {
    size_t i = (size_t)blockIdx.x * blockDim.x + threadIdx.x;
    size_t stride = (size_t)gridDim.x * blockDim.x;
    size_t n4 = (size_t)N_NODES * (D / 4);
    float4 z = make_float4(0.f, 0.f, 0.f, 0.f);
    for (size_t j = i; j < n4; j += stride) g_agg4[j] = z;
    for (size_t j = i; j < (size_t)N_NODES; j += stride) g_cnt[j] = 0;

    // W prep: 4096 work items (n in [0,128), k-group of 8 in [0,32))
    for (size_t id = i; id < 128 * 32; id += stride) {
        int n  = (int)(id >> 5);
        int k0 = (int)(id & 31) * 8;
        unsigned short hi[8], lo[8];
#pragma unroll
        for (int j = 0; j < 8; j++) {
            float v = W[(size_t)(k0 + j) * 128 + n];      // W[k][n]
            __nv_bfloat16 h = __float2bfloat16(v);
            __nv_bfloat16 l = __float2bfloat16(v - __bfloat162float(h));
            hi[j] = __bfloat16_as_ushort(h);
            lo[j] = __bfloat16_as_ushort(l);
        }
        g_bhi16[n * 32 + (k0 >> 3)] = *reinterpret_cast<uint4*>(hi);
        g_blo16[n * 32 + (k0 >> 3)] = *reinterpret_cast<uint4*>(lo);
    }
}

// ---------------------------------------------------------------------------
// Kernel 2: scatter-add (warp per edge, v4 RED). Index type templated.
// ---------------------------------------------------------------------------
template <typename IdxT>
__global__ void k_scatter(const float* __restrict__ x,
                          const IdxT* __restrict__ ei, int E) {
    int gw   = (int)((blockIdx.x * (size_t)blockDim.x + threadIdx.x) >> 5);
    int lane = threadIdx.x & 31;
    if (gw >= E) return;
    int s = (int)ei[gw];
    int t = (int)ei[(size_t)E + gw];
    float4 m = reinterpret_cast<const float4*>(x + (size_t)s * D)[lane];
    float4* a = g_agg4 + (size_t)t * (D / 4) + lane;
    asm volatile("red.global.add.v4.f32 [%0], {%1, %2, %3, %4};"
                 :: "l"(a), "f"(m.x), "f"(m.y), "f"(m.z), "f"(m.w) : "memory");
    if (lane == 0) atomicAdd(&g_cnt[t], 1);
}

// ---------------------------------------------------------------------------
// Kernel 3: bf16 mma.sync GEMM, fused fp32->hi/lo split + inline mean scale.
// out = [x | agg/max(cnt,1)] @ W via D = Ahi Bhi + Ahi Blo + Alo Bhi.
// ---------------------------------------------------------------------------
__global__ void __launch_bounds__(256)
k_gemm_mma(const float* __restrict__ x, float* __restrict__ out) {
    extern __shared__ char smem[];
    const uint32_t sbase = smem_u32(smem);
    const int tid  = threadIdx.x;
    const int wid  = tid >> 5;
    const int lane = tid & 31;
    const int wm   = wid >> 1;          // 0..3 -> m offset 32*wm
    const int wn   = wid & 1;           // 0..1 -> n offset 64*wn
    const int tile = blockIdx.x;

    // ---- load all of B (hi+lo) into smem with padding ----
    {
        uint4* bh = reinterpret_cast<uint4*>(smem + OFF_BHI);
        uint4* bl = reinterpret_cast<uint4*>(smem + OFF_BLO);
        for (int i = tid; i < 4096; i += 256) {
            int row = i >> 5, c16 = i & 31;
            bh[row * 33 + c16] = g_bhi16[i];
            bl[row * 33 + c16] = g_blo16[i];
        }
    }

    // ---- A loader mapping: thread -> row tid/2, 32 cols at (tid&1)*32 ----
    const int ar  = tid >> 1;
    const int acb = (tid & 1) * 32;
    const int gr  = tile * 128 + ar;
    const bool valid = gr < N_NODES;
    float myrinv = 0.f;
    if (valid) {
        int c = g_cnt[gr];
        myrinv = 1.0f / (float)(c > 0 ? c : 1);
    }

    // load chunk c of A into registers, split, store into smem buffer buf
    auto load_store_chunk = [&](int c, int buf) {
        const float* src;
        float prescale;
        if (c < 2) { src = x + (size_t)gr * D + c * 64 + acb; prescale = 1.f; }
        else { src = reinterpret_cast<const float*>(g_agg4) + (size_t)gr * D + (c - 2) * 64 + acb;
               prescale = myrinv; }
        uint4* dh = reinterpret_cast<uint4*>(smem + OFF_A(buf));
        uint4* dl = reinterpret_cast<uint4*>(smem + OFF_A(buf) + A_MAT_BYTES);
#pragma unroll
        for (int g = 0; g < 4; g++) {
            float f[8];
            if (valid) {
                *reinterpret_cast<float4*>(f)     = reinterpret_cast<const float4*>(src)[2 * g];
                *reinterpret_cast<float4*>(f + 4) = reinterpret_cast<const float4*>(src)[2 * g + 1];
            } else {
#pragma unroll
                for (int j = 0; j < 8; j++) f[j] = 0.f;
            }
            unsigned short hi[8], lo[8];
#pragma unroll
            for (int j = 0; j < 8; j++) {
                float v = f[j] * prescale;
                __nv_bfloat16 h = __float2bfloat16(v);
                __nv_bfloat16 l = __float2bfloat16(v - __bfloat162float(h));
                hi[j] = __bfloat16_as_ushort(h);
                lo[j] = __bfloat16_as_ushort(l);
            }
            int idx = ar * 9 + (acb >> 3) + g;   // SA*2/16 = 9 uint4 per row
            dh[idx] = *reinterpret_cast<uint4*>(hi);
            dl[idx] = *reinterpret_cast<uint4*>(lo);
        }
    };

    load_store_chunk(0, 0);
    __syncthreads();

    // ---- ldmatrix lane addressing ----
    const int rL   = (lane & 7) + ((lane >> 3) & 1) * 8;  // row within 16
    const int col8 = (lane >> 4) * 8;                     // k half
    const uint32_t aBaseRow = (uint32_t)((32 * wm + rL) * SA + col8) * 2;
    const uint32_t bHiBase  = sbase + OFF_BHI + (uint32_t)((64 * wn + rL) * SB + col8) * 2;

    float acc[2][8][4];
#pragma unroll
    for (int mi = 0; mi < 2; mi++)
#pragma unroll
        for (int ni = 0; ni < 8; ni++)
#pragma unroll
            for (int q = 0; q < 4; q++) acc[mi][ni][q] = 0.f;

    for (int c = 0; c < 4; c++) {
        // fill next chunk's buffer (other buffer; safe to write now)
        if (c < 3) load_store_chunk(c + 1, (c + 1) & 1);

        const uint32_t aHi = sbase + OFF_A(c & 1) + aBaseRow;
        const uint32_t aLo = aHi + A_MAT_BYTES;
        const uint32_t bC  = (uint32_t)c * 128;    // chunk k-offset: 64 bf16 = 128 B
#pragma unroll
        for (int ks = 0; ks < 4; ks++) {
            const uint32_t ko = ks * 32;               // 16 bf16 = 32 bytes
            uint32_t ahi[2][4], alo[2][4];
            LDSM4(ahi[0][0], ahi[0][1], ahi[0][2], ahi[0][3], aHi + ko);
            LDSM4(ahi[1][0], ahi[1][1], ahi[1][2], ahi[1][3], aHi + ko + 16 * SA * 2);
            LDSM4(alo[0][0], alo[0][1], alo[0][2], alo[0][3], aLo + ko);
            LDSM4(alo[1][0], alo[1][1], alo[1][2], alo[1][3], aLo + ko + 16 * SA * 2);
            // interleave B loads with MMAs to cap live B registers
#pragma unroll
            for (int nb = 0; nb < 4; nb++) {
                uint32_t bhi0[2], bhi1[2], blo0[2], blo1[2];
                {
                    uint32_t t0, t1, t2, t3;
                    LDSM4(t0, t1, t2, t3, bHiBase + bC + ko + nb * 16 * SB * 2);
                    bhi0[0] = t0; bhi0[1] = t2; bhi1[0] = t1; bhi1[1] = t3;
                    LDSM4(t0, t1, t2, t3, bHiBase + B_MAT_BYTES + bC + ko + nb * 16 * SB * 2);
                    blo0[0] = t0; blo0[1] = t2; blo1[0] = t1; blo1[1] = t3;
                }
#pragma unroll
                for (int mi = 0; mi < 2; mi++) {
                    MMA(acc[mi][2 * nb],     ahi[mi], bhi0);
                    MMA(acc[mi][2 * nb],     ahi[mi], blo0);
                    MMA(acc[mi][2 * nb],     alo[mi], bhi0);
                    MMA(acc[mi][2 * nb + 1], ahi[mi], bhi1);
                    MMA(acc[mi][2 * nb + 1], ahi[mi], blo1);
                    MMA(acc[mi][2 * nb + 1], alo[mi], bhi1);
                }
            }
        }
        __syncthreads();
    }

    // ---- epilogue: fp32 stores ----
#pragma unroll
    for (int mi = 0; mi < 2; mi++) {
        int r0 = tile * 128 + 32 * wm + 16 * mi + (lane >> 2);
        int r1 = r0 + 8;
#pragma unroll
        for (int ni = 0; ni < 8; ni++) {
            int colo = 64 * wn + 8 * ni + 2 * (lane & 3);
            if (r0 < N_NODES)
                *reinterpret_cast<float2*>(out + (size_t)r0 * 128 + colo) =
                    make_float2(acc[mi][ni][0], acc[mi][ni][1]);
            if (r1 < N_NODES)
                *reinterpret_cast<float2*>(out + (size_t)r1 * 128 + colo) =
                    make_float2(acc[mi][ni][2], acc[mi][ni][3]);
        }
    }
}

// ---------------------------------------------------------------------------
extern "C" void kernel_launch(void* const* d_in, const int* in_sizes, int n_in,
                              void* d_out, int out_size) {
    const float* x = (const float*)d_in[0];
    const float* W = (const float*)d_in[2];
    float* out = (float*)d_out;

    int nelem = in_sizes[1];
    int E; bool is64;
    if (nelem == 2 * 800000)      { E = 800000;    is64 = false; }
    else if (nelem == 4 * 800000) { E = 800000;    is64 = true;  }
    else                          { E = nelem / 2; is64 = false; }

    cudaFuncSetAttribute(k_gemm_mma, cudaFuncAttributeMaxDynamicSharedMemorySize, SMEM_TOT);

    k_init<<<592, 256>>>(W);
    size_t threads_total = (size_t)E * 32;
    unsigned blocks = (unsigned)((threads_total + 255) / 256);
    if (is64)
        k_scatter<long long><<<blocks, 256>>>(x, (const long long*)d_in[1], E);
    else
        k_scatter<int><<<blocks, 256>>>(x, (const int*)d_in[1], E);
    k_gemm_mma<<<TILES, 256, SMEM_TOT>>>(x, out);
}

// round 10
// speedup vs baseline: 1.2955x; 1.0593x over previous
#include <cuda_runtime.h>
#include <cuda_bf16.h>
#include <cstdint>

#define N_NODES 50000
#define D 128
#define TILES 391            // ceil(50000/128)

// ---------------- scratch (__device__ globals; alloc-free rule) ------------
__device__ float4 g_agg4[(size_t)N_NODES * (D / 4)];
__device__ int    g_cnt[N_NODES];
// W^T split: [128 n][256 k] bf16 hi/lo, row-major. 128*32 = 4096 uint4 each.
__device__ uint4  g_bhi16[4096];
__device__ uint4  g_blo16[4096];

// ---------------- GEMM geometry (N-split: 128x64 tile per CTA) -------------
#define SA 40                 // A smem row stride (bf16): 32 + 8 pad
#define SB 264                // B smem row stride (bf16): 256 + 8 pad
#define A_MAT_BYTES (128 * SA * 2)        // 10240
#define B_MAT_BYTES (64 * SB * 2)         // 33792 (64 n-rows per CTA)
#define OFF_A(buf)  ((buf) * 2 * A_MAT_BYTES)        // hi +0, lo +A_MAT_BYTES
#define OFF_BHI     (2 * 2 * A_MAT_BYTES)            // 40960
#define OFF_BLO     (OFF_BHI + B_MAT_BYTES)          // 74752
#define SMEM_TOT    (OFF_BLO + B_MAT_BYTES)          // 108544 -> 2 CTAs/SM

__device__ __forceinline__ uint32_t smem_u32(const void* p) {
    uint32_t a;
    asm("{ .reg .u64 t; cvta.to.shared.u64 t, %1; cvt.u32.u64 %0, t; }"
        : "=r"(a) : "l"(p));
    return a;
}

#define LDSM4(r0, r1, r2, r3, addr)                                          \
    asm volatile("ldmatrix.sync.aligned.m8n8.x4.shared.b16 {%0,%1,%2,%3}, [%4];" \
                 : "=r"(r0), "=r"(r1), "=r"(r2), "=r"(r3) : "r"(addr))

#define MMA(d, a, b)                                                          \
    asm volatile("mma.sync.aligned.m16n8k16.row.col.f32.bf16.bf16.f32 "       \
                 "{%0,%1,%2,%3}, {%4,%5,%6,%7}, {%8,%9}, {%0,%1,%2,%3};"      \
                 : "+f"((d)[0]), "+f"((d)[1]), "+f"((d)[2]), "+f"((d)[3])     \
                 : "r"((a)[0]), "r"((a)[1]), "r"((a)[2]), "r"((a)[3]),        \
                   "r"((b)[0]), "r"((b)[1]))

// ---------------------------------------------------------------------------
// Kernel 1: init — zero agg + counts AND build W^T bf16 hi/lo blobs
// ---------------------------------------------------------------------------
__global__ void k_init(const float* __restrict__ W) {
    size_t i = (size_t)blockIdx.x * blockDim.x + threadIdx.x;
    size_t stride = (size_t)gridDim.x * blockDim.x;
    size_t n4 = (size_t)N_NODES * (D / 4);
    float4 z = make_float4(0.f, 0.f, 0.f, 0.f);
    for (size_t j = i; j < n4; j += stride) g_agg4[j] = z;
    for (size_t j = i; j < (size_t)N_NODES; j += stride) g_cnt[j] = 0;

    for (size_t id = i; id < 128 * 32; id += stride) {
        int n  = (int)(id >> 5);
        int k0 = (int)(id & 31) * 8;
        unsigned short hi[8], lo[8];
#pragma unroll
        for (int j = 0; j < 8; j++) {
            float v = W[(size_t)(k0 + j) * 128 + n];      // W[k][n]
            __nv_bfloat16 h = __float2bfloat16(v);
            __nv_bfloat16 l = __float2bfloat16(v - __bfloat162float(h));
            hi[j] = __bfloat16_as_ushort(h);
            lo[j] = __bfloat16_as_ushort(l);
        }
        g_bhi16[n * 32 + (k0 >> 3)] = *reinterpret_cast<uint4*>(hi);
        g_blo16[n * 32 + (k0 >> 3)] = *reinterpret_cast<uint4*>(lo);
    }
}

// ---------------------------------------------------------------------------
// Kernel 2: scatter-add (warp per edge, v4 RED). Index type templated.
// ---------------------------------------------------------------------------
template <typename IdxT>
__global__ void k_scatter(const float* __restrict__ x,
                          const IdxT* __restrict__ ei, int E) {
    int gw   = (int)((blockIdx.x * (size_t)blockDim.x + threadIdx.x) >> 5);
    int lane = threadIdx.x & 31;
    if (gw >= E) return;
    int s = (int)ei[gw];
    int t = (int)ei[(size_t)E + gw];
    float4 m = reinterpret_cast<const float4*>(x + (size_t)s * D)[lane];
    float4* a = g_agg4 + (size_t)t * (D / 4) + lane;
    asm volatile("red.global.add.v4.f32 [%0], {%1, %2, %3, %4};"
                 :: "l"(a), "f"(m.x), "f"(m.y), "f"(m.z), "f"(m.w) : "memory");
    if (lane == 0) atomicAdd(&g_cnt[t], 1);
}

// ---------------------------------------------------------------------------
// Kernel 3: N-split bf16 mma.sync GEMM. Each CTA: 128 rows x 64 cols,
// 2 CTAs per tile (blockIdx: tile = bx>>1, nh = bx&1). 2 CTAs/SM occupancy.
// D = Ahi Bhi + Ahi Blo + Alo Bhi, fused fp32->hi/lo split + mean scale.
// A in K-chunks of 32 (8 chunks), double-buffered; B half resident.
// ---------------------------------------------------------------------------
__global__ void __launch_bounds__(256)
k_gemm_mma(const float* __restrict__ x, float* __restrict__ out) {
    extern __shared__ char smem[];
    const uint32_t sbase = smem_u32(smem);
    const int tid  = threadIdx.x;
    const int wid  = tid >> 5;          // 0..7 -> 16-row slab
    const int lane = tid & 31;
    const int tile = blockIdx.x >> 1;
    const int nh   = blockIdx.x & 1;    // which 64-col half of B

    // ---- load this CTA's B half (hi+lo), rows [64*nh, 64*nh+64) ----
    {
        uint4* bh = reinterpret_cast<uint4*>(smem + OFF_BHI);
        uint4* bl = reinterpret_cast<uint4*>(smem + OFF_BLO);
        for (int i = tid; i < 2048; i += 256) {
            int row = i >> 5, c16 = i & 31;
            bh[row * 33 + c16] = g_bhi16[(64 * nh + row) * 32 + c16];
            bl[row * 33 + c16] = g_blo16[(64 * nh + row) * 32 + c16];
        }
    }

    // ---- A loader: thread -> row tid/2, 16 cols at (tid&1)*16 ----
    const int ar  = tid >> 1;
    const int acb = (tid & 1) * 16;
    const int gr  = tile * 128 + ar;
    const bool valid = gr < N_NODES;
    float myrinv = 0.f;
    if (valid) {
        int c = g_cnt[gr];
        myrinv = 1.0f / (float)(c > 0 ? c : 1);
    }

    float4 pre[4];
    auto preload = [&](int c) {
        const float* src;
        if (c < 4) src = x + (size_t)gr * D + c * 32 + acb;
        else       src = reinterpret_cast<const float*>(g_agg4) + (size_t)gr * D + (c - 4) * 32 + acb;
        if (valid) {
#pragma unroll
            for (int j = 0; j < 4; j++) pre[j] = reinterpret_cast<const float4*>(src)[j];
        } else {
#pragma unroll
            for (int j = 0; j < 4; j++) pre[j] = make_float4(0.f, 0.f, 0.f, 0.f);
        }
    };
    auto store_chunk = [&](int c, int buf) {
        float prescale = (c < 4) ? 1.f : myrinv;
        uint4* dh = reinterpret_cast<uint4*>(smem + OFF_A(buf));
        uint4* dl = reinterpret_cast<uint4*>(smem + OFF_A(buf) + A_MAT_BYTES);
#pragma unroll
        for (int g = 0; g < 2; g++) {
            float f[8];
            *reinterpret_cast<float4*>(f)     = pre[2 * g];
            *reinterpret_cast<float4*>(f + 4) = pre[2 * g + 1];
            unsigned short hi[8], lo[8];
#pragma unroll
            for (int j = 0; j < 8; j++) {
                float v = f[j] * prescale;
                __nv_bfloat16 h = __float2bfloat16(v);
                __nv_bfloat16 l = __float2bfloat16(v - __bfloat162float(h));
                hi[j] = __bfloat16_as_ushort(h);
                lo[j] = __bfloat16_as_ushort(l);
            }
            int idx = ar * 5 + (acb >> 3) + g;   // SA*2/16 = 5 uint4 per row
            dh[idx] = *reinterpret_cast<uint4*>(hi);
            dl[idx] = *reinterpret_cast<uint4*>(lo);
        }
    };

    preload(0);
    store_chunk(0, 0);
    __syncthreads();

    // ---- ldmatrix lane addressing ----
    const int rL   = (lane & 7) + ((lane >> 3) & 1) * 8;  // row within 16
    const int col8 = (lane >> 4) * 8;                     // k half (0/8)
    const uint32_t aBaseRow = (uint32_t)((16 * wid + rL) * SA + col8) * 2;
    const uint32_t bHiBase  = sbase + OFF_BHI + (uint32_t)(rL * SB + col8) * 2;

    float acc[8][4];
#pragma unroll
    for (int ni = 0; ni < 8; ni++)
#pragma unroll
        for (int q = 0; q < 4; q++) acc[ni][q] = 0.f;

    for (int c = 0; c < 8; c++) {
        if (c < 7) preload(c + 1);

        const uint32_t aHi = sbase + OFF_A(c & 1) + aBaseRow;
        const uint32_t aLo = aHi + A_MAT_BYTES;
        const uint32_t bC  = (uint32_t)c * 64;     // chunk k-offset: 32 bf16 = 64 B
#pragma unroll
        for (int ks = 0; ks < 2; ks++) {
            const uint32_t ko = ks * 32;           // 16 bf16 = 32 bytes
            uint32_t ahi[4], alo[4];
            LDSM4(ahi[0], ahi[1], ahi[2], ahi[3], aHi + ko);
            LDSM4(alo[0], alo[1], alo[2], alo[3], aLo + ko);
#pragma unroll
            for (int nb = 0; nb < 4; nb++) {
                uint32_t bhi0[2], bhi1[2], blo0[2], blo1[2];
                {
                    uint32_t t0, t1, t2, t3;
                    LDSM4(t0, t1, t2, t3, bHiBase + bC + ko + nb * 16 * SB * 2);
                    bhi0[0] = t0; bhi0[1] = t2; bhi1[0] = t1; bhi1[1] = t3;
                    LDSM4(t0, t1, t2, t3, bHiBase + (OFF_BLO - OFF_BHI) + bC + ko + nb * 16 * SB * 2);
                    blo0[0] = t0; blo0[1] = t2; blo1[0] = t1; blo1[1] = t3;
                }
                MMA(acc[2 * nb],     ahi, bhi0);
                MMA(acc[2 * nb],     ahi, blo0);
                MMA(acc[2 * nb],     alo, bhi0);
                MMA(acc[2 * nb + 1], ahi, bhi1);
                MMA(acc[2 * nb + 1], ahi, blo1);
                MMA(acc[2 * nb + 1], alo, bhi1);
            }
        }

        if (c < 7) store_chunk(c + 1, (c + 1) & 1);
        __syncthreads();
    }

    // ---- epilogue: fp32 stores (rows 16*wid.., cols nh*64..) ----
    {
        int r0 = tile * 128 + 16 * wid + (lane >> 2);
        int r1 = r0 + 8;
#pragma unroll
        for (int ni = 0; ni < 8; ni++) {
            int colo = nh * 64 + 8 * ni + 2 * (lane & 3);
            if (r0 < N_NODES)
                *reinterpret_cast<float2*>(out + (size_t)r0 * 128 + colo) =
                    make_float2(acc[ni][0], acc[ni][1]);
            if (r1 < N_NODES)
                *reinterpret_cast<float2*>(out + (size_t)r1 * 128 + colo) =
                    make_float2(acc[ni][2], acc[ni][3]);
        }
    }
}

// ---------------------------------------------------------------------------
extern "C" void kernel_launch(void* const* d_in, const int* in_sizes, int n_in,
                              void* d_out, int out_size) {
    const float* x = (const float*)d_in[0];
    const float* W = (const float*)d_in[2];
    float* out = (float*)d_out;

    int nelem = in_sizes[1];
    int E; bool is64;
    if (nelem == 2 * 800000)      { E = 800000;    is64 = false; }
    else if (nelem == 4 * 800000) { E = 800000;    is64 = true;  }
    else                          { E = nelem / 2; is64 = false; }

    cudaFuncSetAttribute(k_gemm_mma, cudaFuncAttributeMaxDynamicSharedMemorySize, SMEM_TOT);

    k_init<<<592, 256>>>(W);
    size_t threads_total = (size_t)E * 32;
    unsigned blocks = (unsigned)((threads_total + 255) / 256);
    if (is64)
        k_scatter<long long><<<blocks, 256>>>(x, (const long long*)d_in[1], E);
    else
        k_scatter<int><<<blocks, 256>>>(x, (const int*)d_in[1], E);
    k_gemm_mma<<<TILES * 2, 256, SMEM_TOT>>>(x, out);
}